// round 10
// baseline (speedup 1.0000x reference)
#include <cuda_runtime.h>
#include <cstdint>

// ---------------------------------------------------------------------------
// 4-layer LSTM (B=128, T=1024, D=128, H=[100,100,200,200]) + dense head.
// R9: GEMMs = R7 scalar fp32 (mma.sync reverted; slower twice on sm_103a).
// Scans restructured to 1024 threads @ <=64 regs: double the warps/SMSP,
// half the per-thread work (gate-pair decomposition). scan200 keeps the
// R7 st.async + mbarrier cluster sync.
// ---------------------------------------------------------------------------

#define TLEN 1024
#define BSZ  128
#define HPAD 256

typedef unsigned long long u64;

__device__ float g_zx[(size_t)BSZ * TLEN * 800];  // x@Wx+b, layout [b][t][j][4]
__device__ float g_seq[(size_t)BSZ * TLEN * 200]; // layer output sequence
__device__ float g_hbuf[BSZ * HPAD];              // final h for dense head

#define FMA2(d, a, b, c) \
    asm("fma.rn.f32x2 %0, %1, %2, %3;" : "=l"(d) : "l"(a), "l"(b), "l"(c))

__device__ __forceinline__ u64 pack2(float lo, float hi) {
    u64 d;
    asm("mov.b64 %0, {%1, %2};" : "=l"(d)
        : "r"(__float_as_uint(lo)), "r"(__float_as_uint(hi)));
    return d;
}
__device__ __forceinline__ float2 unpack2(u64 v) {
    unsigned lo, hi;
    asm("mov.b64 {%0, %1}, %2;" : "=r"(lo), "=r"(hi) : "l"(v));
    return make_float2(__uint_as_float(lo), __uint_as_float(hi));
}

__device__ __forceinline__ float sigm(float x) {
    return __fdividef(1.0f, 1.0f + __expf(-x));
}
__device__ __forceinline__ float tanh_fast(float x) {
    return 1.0f - __fdividef(2.0f, __expf(2.0f * x) + 1.0f);
}

__device__ __forceinline__ void mbar_wait_parity_cluster(uint32_t bar, uint32_t parity) {
    uint32_t done;
    asm volatile(
        "{\n\t.reg .pred p;\n\t"
        "mbarrier.try_wait.parity.acquire.cluster.shared::cta.b64 p, [%1], %2;\n\t"
        "selp.b32 %0, 1, 0, p;\n\t}"
        : "=r"(done) : "r"(bar), "r"(parity) : "memory");
    if (!done) {
        asm volatile(
            "{\n\t.reg .pred P1;\n\t"
            "WAIT_LOOP_%=:\n\t"
            "mbarrier.try_wait.parity.acquire.cluster.shared::cta.b64 P1, [%0], %1, 0x989680;\n\t"
            "@P1 bra.uni WAIT_DONE_%=;\n\t"
            "bra.uni WAIT_LOOP_%=;\n\t"
            "WAIT_DONE_%=:\n\t}"
            :: "r"(bar), "r"(parity) : "memory");
    }
}

// ---------------------------------------------------------------------------
// Precompute GEMM (R7 scalar version, proven): C[M,n] = A@W[.,colmap(n)] + b.
// colmap(n) = (n&3)*Hn + (n>>2). 128x128 tile, 256 thr, 8x8 f32x2 thread
// tile, KC=8 double-buffered.
// ---------------------------------------------------------------------------
template <int K>
__global__ void __launch_bounds__(256, 2)
gemm_x(const float* __restrict__ Ain, const float* __restrict__ W,
       const float* __restrict__ bias, int N, int Hn, int use_seq)
{
    constexpr int KC = 8;
    constexpr int NCHUNK = (K + KC - 1) / KC;

    __shared__ __align__(16) float A_s[2][KC][132];
    __shared__ __align__(16) float W_s[2][KC][132];

    const float* __restrict__ A = use_seq ? g_seq : Ain;
    const int tid = threadIdx.x;
    const int tx = tid & 15, ty = tid >> 4;
    const int m0 = blockIdx.y * 128, n0 = blockIdx.x * 128;

    const int a_row = tid >> 3, a_kk = tid & 7;
    const int w_kk0 = tid >> 7, w_n = tid & 127;
    const int wcol  = n0 + w_n;
    const int wsrc  = (wcol & 3) * Hn + (wcol >> 2);

    float aR[4], wR[4];

    auto ldA = [&](int c) {
        const int k0 = c * KC;
        #pragma unroll
        for (int e = 0; e < 4; ++e) {
            int row = a_row + 32 * e;
            aR[e] = (k0 + a_kk < K) ? A[(size_t)(m0 + row) * K + k0 + a_kk] : 0.0f;
        }
    };
    auto ldW = [&](int c) {
        const int k0 = c * KC;
        #pragma unroll
        for (int e = 0; e < 4; ++e) {
            int kk = 2 * e + w_kk0;
            float v = 0.0f;
            if ((k0 + kk < K) && (wcol < N)) v = W[(size_t)(k0 + kk) * N + wsrc];
            wR[e] = v;
        }
    };
    auto stA = [&](int buf) {
        #pragma unroll
        for (int e = 0; e < 4; ++e) A_s[buf][a_kk][a_row + 32 * e] = aR[e];
    };
    auto stW = [&](int buf) {
        #pragma unroll
        for (int e = 0; e < 4; ++e) W_s[buf][2 * e + w_kk0][w_n] = wR[e];
    };

    ldA(0); ldW(0);
    stA(0); stW(0);
    __syncthreads();

    u64 acc2[4][8];
    #pragma unroll
    for (int mp = 0; mp < 4; ++mp)
        #pragma unroll
        for (int j = 0; j < 8; ++j) acc2[mp][j] = 0ull;

    for (int c = 0; c < NCHUNK; ++c) {
        const int buf = c & 1;
        if (c + 1 < NCHUNK) { ldA(c + 1); ldW(c + 1); }
        #pragma unroll
        for (int k = 0; k < KC; ++k) {
            ulonglong2 ap0 = *reinterpret_cast<const ulonglong2*>(&A_s[buf][k][ty * 8]);
            ulonglong2 ap1 = *reinterpret_cast<const ulonglong2*>(&A_s[buf][k][ty * 8 + 4]);
            float4 w0 = *reinterpret_cast<const float4*>(&W_s[buf][k][tx * 8]);
            float4 w1 = *reinterpret_cast<const float4*>(&W_s[buf][k][tx * 8 + 4]);
            u64 ap[4] = {ap0.x, ap0.y, ap1.x, ap1.y};
            u64 wd[8];
            wd[0] = pack2(w0.x, w0.x); wd[1] = pack2(w0.y, w0.y);
            wd[2] = pack2(w0.z, w0.z); wd[3] = pack2(w0.w, w0.w);
            wd[4] = pack2(w1.x, w1.x); wd[5] = pack2(w1.y, w1.y);
            wd[6] = pack2(w1.z, w1.z); wd[7] = pack2(w1.w, w1.w);
            #pragma unroll
            for (int mp = 0; mp < 4; ++mp)
                #pragma unroll
                for (int j = 0; j < 8; ++j)
                    FMA2(acc2[mp][j], ap[mp], wd[j], acc2[mp][j]);
        }
        if (c + 1 < NCHUNK) { stA(buf ^ 1); stW(buf ^ 1); }
        __syncthreads();
    }

    float accf[8][8];
    #pragma unroll
    for (int mp = 0; mp < 4; ++mp)
        #pragma unroll
        for (int j = 0; j < 8; ++j) {
            float2 t = unpack2(acc2[mp][j]);
            accf[2 * mp][j]     = t.x;
            accf[2 * mp + 1][j] = t.y;
        }

    if (n0 + tx * 8 < N) {
        float b[8];
        #pragma unroll
        for (int j = 0; j < 8; ++j) {
            int cc = n0 + tx * 8 + j;
            b[j] = bias[(cc & 3) * Hn + (cc >> 2)];
        }
        #pragma unroll
        for (int i = 0; i < 8; ++i) {
            size_t off = (size_t)(m0 + ty * 8 + i) * N + (n0 + tx * 8);
            float4 v0 = make_float4(accf[i][0] + b[0], accf[i][1] + b[1],
                                    accf[i][2] + b[2], accf[i][3] + b[3]);
            float4 v1 = make_float4(accf[i][4] + b[4], accf[i][5] + b[5],
                                    accf[i][6] + b[6], accf[i][7] + b[7]);
            *reinterpret_cast<float4*>(&g_zx[off])     = v0;
            *reinterpret_cast<float4*>(&g_zx[off + 4]) = v1;
        }
    }
}

// ---------------------------------------------------------------------------
// H=100 scan: 1 CTA / batch row, 1024 threads (32 warps).
// gemm thread (s<5, g2<2, j<100): k in [20s,20s+20), gates [2g2,2g2+2).
// Weights 20 u64 regs. zp float2 per (s,g2,j). Reduce by tid<100.
// ---------------------------------------------------------------------------
__global__ void __launch_bounds__(1024, 1)
scan100(const float* __restrict__ Wh)
{
    __shared__ __align__(16) float  h_s[104];
    __shared__ __align__(16) float2 zp[5][2][100];

    const int tid = threadIdx.x;
    const int b   = blockIdx.x;
    const int s   = tid / 200;
    const int rmd = tid % 200;
    const int g2  = rmd / 100;
    const int j   = rmd % 100;
    const bool ga  = (tid < 1000);
    const bool red = (tid < 100);

    u64 w2[10][2];   // [k-pair][gate-in-pair]
    if (ga) {
        const int k0 = s * 20;
        #pragma unroll
        for (int kp = 0; kp < 10; ++kp)
            #pragma unroll
            for (int gg = 0; gg < 2; ++gg) {
                const int g = g2 * 2 + gg;
                w2[kp][gg] = pack2(Wh[(k0 + 2 * kp)     * 400 + g * 100 + j],
                                   Wh[(k0 + 2 * kp + 1) * 400 + g * 100 + j]);
            }
    }
    if (red) h_s[j] = 0.0f;
    float c = 0.0f;
    __syncthreads();

    const float* __restrict__ zbase = g_zx + (size_t)b * TLEN * 400;
    float* __restrict__ ybase = g_seq + (size_t)b * TLEN * 100;

    float4 zb = make_float4(0, 0, 0, 0);
    if (red) zb = *reinterpret_cast<const float4*>(zbase + j * 4);

    for (int t = 0; t < TLEN; ++t) {
        float4 zc;
        if (red) {
            zc = zb;
            int tp = (t + 1 < TLEN) ? t + 1 : t;
            zb = *reinterpret_cast<const float4*>(zbase + (size_t)tp * 400 + j * 4);
        }
        if (ga) {
            u64 a0 = 0ull, a1 = 0ull;
            const ulonglong2* hp = reinterpret_cast<const ulonglong2*>(h_s);
            const int qb = s * 5;
            #pragma unroll
            for (int q = 0; q < 5; ++q) {
                ulonglong2 hv = hp[qb + q];
                FMA2(a0, hv.x, w2[2 * q][0], a0);
                FMA2(a1, hv.x, w2[2 * q][1], a1);
                FMA2(a0, hv.y, w2[2 * q + 1][0], a0);
                FMA2(a1, hv.y, w2[2 * q + 1][1], a1);
            }
            float2 p0 = unpack2(a0), p1 = unpack2(a1);
            zp[s][g2][j] = make_float2(p0.x + p0.y, p1.x + p1.y);
        }
        __syncthreads();
        if (red) {
            float z0 = zc.x, z1 = zc.y, z2 = zc.z, z3 = zc.w;
            #pragma unroll
            for (int ss = 0; ss < 5; ++ss) {
                float2 e = zp[ss][0][j];
                float2 o = zp[ss][1][j];
                z0 += e.x; z1 += e.y; z2 += o.x; z3 += o.y;
            }
            float gi = sigm(z0), gf = sigm(z1), gg = tanh_fast(z2), go = sigm(z3);
            c = gf * c + gi * gg;
            float h = go * tanh_fast(c);
            h_s[j] = h;
            ybase[(size_t)t * 100 + j] = h;
        }
        __syncthreads();
    }
}

// ---------------------------------------------------------------------------
// H=200 scan: cluster of 4 CTAs, 1024 threads each. Rank owns j-slice
// [50r,50r+50); cluster owns 4 batch rows. gemm thread (s<10, g2<2, jl<50):
// k in [20s,20s+20), gates [2g2,2g2+2), all 4 rows sequentially.
// Sync: st.async tx-counted DSMEM h broadcast + mbarrier parity wait (R7).
// ---------------------------------------------------------------------------
template <int WRITE_Y>
__global__ void __launch_bounds__(1024, 1) __cluster_dims__(4, 1, 1)
scan200(const float* __restrict__ Wh)
{
    __shared__ __align__(16) float  h_s[2][4][208];    // [buf][row][k]
    __shared__ __align__(16) float2 zp[10][2][4][50];  // [s][g2][row][jl]
    __shared__ __align__(8)  u64    hbar;

    const int tid = threadIdx.x;
    uint32_t rank;
    asm("mov.u32 %0, %%cluster_ctarank;" : "=r"(rank));
    const int cl = blockIdx.x >> 2;

    const int s   = tid / 100;             // 0..9 (tid<1000)
    const int rmd = tid % 100;
    const int g2  = rmd / 50;
    const int jl  = rmd % 50;
    const bool ga  = (tid < 1000);
    const bool red = (tid < 200);          // rr = tid/50, jl = tid%50
    const int  rr  = tid / 50;
    const int  jg  = (int)rank * 50 + jl;

    uint32_t hs_addr, bar_addr;
    {
        const void* p = (const void*)&h_s[0][0][0];
        asm("{ .reg .u64 t; cvta.to.shared.u64 t, %1; cvt.u32.u64 %0, t; }"
            : "=r"(hs_addr) : "l"(p));
        const void* q = (const void*)&hbar;
        asm("{ .reg .u64 t; cvta.to.shared.u64 t, %1; cvt.u32.u64 %0, t; }"
            : "=r"(bar_addr) : "l"(q));
    }

    u64 w2[10][2];   // [k-pair][gate-in-pair] for (s, g2, jg)
    if (ga) {
        const int k0 = s * 20;
        #pragma unroll
        for (int kp = 0; kp < 10; ++kp)
            #pragma unroll
            for (int gg = 0; gg < 2; ++gg) {
                const int g = g2 * 2 + gg;
                w2[kp][gg] = pack2(Wh[(k0 + 2 * kp)     * 800 + g * 200 + jg],
                                   Wh[(k0 + 2 * kp + 1) * 800 + g * 200 + jg]);
            }
    }
    for (int i = tid; i < 2 * 4 * 208; i += 1024) (&h_s[0][0][0])[i] = 0.0f;
    if (tid == 0) {
        asm volatile("mbarrier.init.shared.b64 [%0], %1;"
                     :: "r"(bar_addr), "r"(1u) : "memory");
    }
    float c = 0.0f;
    __syncthreads();
    asm volatile("barrier.cluster.arrive.aligned;" ::: "memory");
    asm volatile("barrier.cluster.wait.aligned;" ::: "memory");

    const int b = cl * 4 + rr;             // batch row for reduce role
    const float* __restrict__ zbase = g_zx + (size_t)b * TLEN * 800;
    float* __restrict__ ybase = g_seq + (size_t)b * TLEN * 200;

    float4 zb = make_float4(0, 0, 0, 0);
    if (red) zb = *reinterpret_cast<const float4*>(zbase + jg * 4);

    constexpr uint32_t TX_BYTES = 4u * 200u * 4u;   // 4 source CTAs x 200 floats

    for (int t = 0; t < TLEN; ++t) {
        const int cur = t & 1, nxt = cur ^ 1;
        if (tid == 0) {
            asm volatile("mbarrier.arrive.expect_tx.shared.b64 _, [%0], %1;"
                         :: "r"(bar_addr), "r"(TX_BYTES) : "memory");
        }
        float4 zc;
        if (red) {
            zc = zb;
            int tp = (t + 1 < TLEN) ? t + 1 : t;
            zb = *reinterpret_cast<const float4*>(zbase + (size_t)tp * 800 + jg * 4);
        }
        if (ga) {
            const int qb = s * 5;
            #pragma unroll
            for (int r2 = 0; r2 < 4; ++r2) {
                u64 a0 = 0ull, a1 = 0ull;
                const ulonglong2* hp =
                    reinterpret_cast<const ulonglong2*>(&h_s[cur][r2][0]);
                #pragma unroll
                for (int q = 0; q < 5; ++q) {
                    ulonglong2 hv = hp[qb + q];
                    FMA2(a0, hv.x, w2[2 * q][0], a0);
                    FMA2(a1, hv.x, w2[2 * q][1], a1);
                    FMA2(a0, hv.y, w2[2 * q + 1][0], a0);
                    FMA2(a1, hv.y, w2[2 * q + 1][1], a1);
                }
                float2 p0 = unpack2(a0), p1 = unpack2(a1);
                zp[s][g2][r2][jl] = make_float2(p0.x + p0.y, p1.x + p1.y);
            }
        }
        __syncthreads();
        if (red) {
            float z0 = zc.x, z1 = zc.y, z2 = zc.z, z3 = zc.w;
            #pragma unroll
            for (int ss = 0; ss < 10; ++ss) {
                float2 e = zp[ss][0][rr][jl];
                float2 o = zp[ss][1][rr][jl];
                z0 += e.x; z1 += e.y; z2 += o.x; z3 += o.y;
            }
            float gi = sigm(z0), gf = sigm(z1), gg = tanh_fast(z2), go = sigm(z3);
            c = gf * c + gi * gg;
            float h = go * tanh_fast(c);

            uint32_t laddr = hs_addr + (uint32_t)((nxt * 4 + rr) * 208 + jg) * 4u;
            #pragma unroll
            for (int p = 0; p < 4; ++p) {
                uint32_t rdata, rbar;
                asm("mapa.shared::cluster.u32 %0, %1, %2;"
                    : "=r"(rdata) : "r"(laddr), "r"(p));
                asm("mapa.shared::cluster.u32 %0, %1, %2;"
                    : "=r"(rbar) : "r"(bar_addr), "r"(p));
                asm volatile(
                    "st.async.shared::cluster.mbarrier::complete_tx::bytes.f32 "
                    "[%0], %1, [%2];"
                    :: "r"(rdata), "f"(h), "r"(rbar) : "memory");
            }
            if (WRITE_Y) ybase[(size_t)t * 200 + jg] = h;
            if (t == TLEN - 1) g_hbuf[b * HPAD + jg] = h;
        }
        mbar_wait_parity_cluster(bar_addr, (uint32_t)(t & 1));
    }

    asm volatile("barrier.cluster.arrive.aligned;" ::: "memory");
    asm volatile("barrier.cluster.wait.aligned;" ::: "memory");
}

// Final dense: out[b, o] = h_last[b, :200] @ Wd + bd.
__global__ void dense_kernel(const float* __restrict__ Wd,
                             const float* __restrict__ bd,
                             float* __restrict__ out)
{
    int idx = blockIdx.x * blockDim.x + threadIdx.x;
    if (idx >= BSZ * 6) return;
    int b = idx / 6, o = idx - b * 6;
    const float* h = g_hbuf + b * HPAD;
    float s = bd[o];
    #pragma unroll 8
    for (int k = 0; k < 200; ++k) s += h[k] * Wd[k * 6 + o];
    out[idx] = s;
}

extern "C" void kernel_launch(void* const* d_in, const int* in_sizes, int n_in,
                              void* d_out, int out_size)
{
    const float* xs  = (const float*)d_in[0];
    const float* Wx0 = (const float*)d_in[1];
    const float* Wh0 = (const float*)d_in[2];
    const float* b0  = (const float*)d_in[3];
    const float* Wx1 = (const float*)d_in[4];
    const float* Wh1 = (const float*)d_in[5];
    const float* b1  = (const float*)d_in[6];
    const float* Wx2 = (const float*)d_in[7];
    const float* Wh2 = (const float*)d_in[8];
    const float* b2  = (const float*)d_in[9];
    const float* Wx3 = (const float*)d_in[10];
    const float* Wh3 = (const float*)d_in[11];
    const float* b3  = (const float*)d_in[12];
    const float* Wd  = (const float*)d_in[13];
    const float* bd  = (const float*)d_in[14];

    const dim3 gN400(4, 1024);   // ceil(400/128) x (131072/128)
    const dim3 gN800(7, 1024);   // ceil(800/128)

    // L0
    gemm_x<128><<<gN400, 256>>>(xs, Wx0, b0, 400, 100, 0);
    scan100<<<BSZ, 1024>>>(Wh0);
    // L1
    gemm_x<100><<<gN400, 256>>>(nullptr, Wx1, b1, 400, 100, 1);
    scan100<<<BSZ, 1024>>>(Wh1);
    // L2
    gemm_x<100><<<gN800, 256>>>(nullptr, Wx2, b2, 800, 200, 1);
    scan200<1><<<BSZ, 1024>>>(Wh2);
    // L3
    gemm_x<200><<<gN800, 256>>>(nullptr, Wx3, b3, 800, 200, 1);
    scan200<0><<<BSZ, 1024>>>(Wh3);
    // head
    dense_kernel<<<3, 256>>>(Wd, bd, (float*)d_out);
}